// round 8
// baseline (speedup 1.0000x reference)
#include <cuda_runtime.h>
#include <cuda_fp16.h>
#include <stdint.h>

#define B_   32
#define C_   128
#define H_   56
#define W_   56
#define O_   256
#define HW_  3136
#define NPOS 100352
#define TROW 28

// Scratch (__device__ globals, allocation-free rule)
__device__ __align__(16) int8_t g_qx[(size_t)NPOS * C_];        // [pos][c] NHWC int8
__device__ __align__(16) __half g_U[(size_t)16 * O_ * C_];      // [tap][o][c] fp16
__device__ float g_sw[O_];

// ---------------------------------------------------------------------------
// PTX helpers (base ISA; valid on plain sm_103 target)
// ---------------------------------------------------------------------------
__device__ __forceinline__ void cp16(uint32_t dst, const void* src) {
    asm volatile("cp.async.cg.shared.global [%0], [%1], 16;\n"
                 :: "r"(dst), "l"(__cvta_generic_to_global(src)));
}
__device__ __forceinline__ void cp16z(uint32_t dst, const void* src, uint32_t sz) {
    asm volatile("cp.async.cg.shared.global [%0], [%1], 16, %2;\n"
                 :: "r"(dst), "l"(__cvta_generic_to_global(src)), "r"(sz));
}
__device__ __forceinline__ void cp_commit() { asm volatile("cp.async.commit_group;\n" ::); }
template<int N> __device__ __forceinline__ void cp_wait() {
    asm volatile("cp.async.wait_group %0;\n" :: "n"(N));
}
__device__ __forceinline__ void ldsm4(uint32_t* r, uint32_t addr) {
    asm volatile("ldmatrix.sync.aligned.m8n8.x4.shared.b16 {%0,%1,%2,%3}, [%4];\n"
                 : "=r"(r[0]), "=r"(r[1]), "=r"(r[2]), "=r"(r[3]) : "r"(addr));
}
__device__ __forceinline__ void mma_f16(float* c, const uint32_t* a, uint32_t b0, uint32_t b1) {
    asm volatile("mma.sync.aligned.m16n8k16.row.col.f32.f16.f16.f32 "
                 "{%0,%1,%2,%3}, {%4,%5,%6,%7}, {%8,%9}, {%0,%1,%2,%3};\n"
                 : "+f"(c[0]), "+f"(c[1]), "+f"(c[2]), "+f"(c[3])
                 : "r"(a[0]), "r"(a[1]), "r"(a[2]), "r"(a[3]), "r"(b0), "r"(b1));
}
__device__ __forceinline__ uint32_t lds32(uint32_t addr) {
    uint32_t v;
    asm volatile("ld.shared.b32 %0, [%1];" : "=r"(v) : "r"(addr));
    return v;
}
__device__ __forceinline__ void sts32(uint32_t addr, uint32_t v) {
    asm volatile("st.shared.b32 [%0], %1;" :: "r"(addr), "r"(v));
}
__device__ __forceinline__ void sts64v(uint32_t addr, uint32_t a, uint32_t b) {
    asm volatile("st.shared.v2.b32 [%0], {%1,%2};" :: "r"(addr), "r"(a), "r"(b));
}
__device__ __forceinline__ uint32_t prmt0(uint32_t a, uint32_t c) {
    uint32_t d;
    asm("prmt.b32 %0, %1, 0, %2;" : "=r"(d) : "r"(a), "r"(c));
    return d;
}

// ---------------------------------------------------------------------------
// 1) Quantize x: NCHW fp32 -> NHWC int8. 64 pos x 4 c-groups per 256-thr block.
// ---------------------------------------------------------------------------
__global__ __launch_bounds__(256) void quant_x_kernel(const float* __restrict__ x,
                                                      const float* __restrict__ sxp)
{
    int t = threadIdx.x;
    float s = *sxp;
    int pos = blockIdx.x * 64 + (t & 63);
    int g   = t >> 6;
    int b = pos / HW_, sp = pos - b * HW_;
    const float* xp = x + (size_t)b * C_ * HW_ + (size_t)(g * 32) * HW_ + sp;

    uint32_t pk[8];
#pragma unroll
    for (int q = 0; q < 8; q++) {
        uint32_t p = 0;
#pragma unroll
        for (int bb = 0; bb < 4; bb++) {
            float v = xp[(q * 4 + bb) * HW_];
            int qi = (int)rintf(v / s);          // true div + RNE == jnp.round(x/s)
            qi = max(-127, min(127, qi));
            p |= (uint32_t)(qi & 0xFF) << (8 * bb);
        }
        pk[q] = p;
    }
    uint4* dst = (uint4*)(g_qx + (size_t)pos * C_ + g * 32);
    dst[0] = make_uint4(pk[0], pk[1], pk[2], pk[3]);
    dst[1] = make_uint4(pk[4], pk[5], pk[6], pk[7]);
}

// ---------------------------------------------------------------------------
// 2) weight: per-o scale = max|w|/127, quantize, Winograd filter transform
//    -> g_U[tap][o][c]  (fp16 exact: quarter-multiples, |.| <= 286)
// ---------------------------------------------------------------------------
__global__ __launch_bounds__(128) void wino_w_kernel(const float* __restrict__ w)
{
    int o = blockIdx.x, t = threadIdx.x;
    const float* wo = w + (size_t)o * 1152;

    float m = 0.f;
    for (int i = t; i < 1152; i += 128) m = fmaxf(m, fabsf(wo[i]));
#pragma unroll
    for (int off = 16; off; off >>= 1) m = fmaxf(m, __shfl_xor_sync(0xFFFFFFFFu, m, off));
    __shared__ float red[4];
    if ((t & 31) == 0) red[t >> 5] = m;
    __syncthreads();
    m = fmaxf(fmaxf(red[0], red[1]), fmaxf(red[2], red[3]));
    float scale = m / 127.0f;
    if (t == 0) g_sw[o] = scale;

    int c = t;
    float g[3][3];
#pragma unroll
    for (int kh = 0; kh < 3; kh++)
#pragma unroll
        for (int kw = 0; kw < 3; kw++) {
            float q = rintf(wo[c * 9 + kh * 3 + kw] / scale);
            g[kh][kw] = fminf(fmaxf(q, -127.f), 127.f);
        }
    float f[4][3];
#pragma unroll
    for (int j = 0; j < 3; j++) {
        f[0][j] = g[0][j];
        f[1][j] = (g[0][j] + g[1][j] + g[2][j]) * 0.5f;
        f[2][j] = (g[0][j] - g[1][j] + g[2][j]) * 0.5f;
        f[3][j] = g[2][j];
    }
#pragma unroll
    for (int r = 0; r < 4; r++) {
        float u0 = f[r][0];
        float u1 = (f[r][0] + f[r][1] + f[r][2]) * 0.5f;
        float u2 = (f[r][0] - f[r][1] + f[r][2]) * 0.5f;
        float u3 = f[r][2];
        g_U[((size_t)(r * 4 + 0) * O_ + o) * C_ + c] = __float2half_rn(u0);
        g_U[((size_t)(r * 4 + 1) * O_ + o) * C_ + c] = __float2half_rn(u1);
        g_U[((size_t)(r * 4 + 2) * O_ + o) * C_ + c] = __float2half_rn(u2);
        g_U[((size_t)(r * 4 + 3) * O_ + o) * C_ + c] = __float2half_rn(u3);
    }
}

// ---------------------------------------------------------------------------
// 3) Fused Winograd GEMM: input transform generated from int8 patch in SMEM.
//    CTA = 112 tiles (4 tile-rows of one image) x 64 o, 448 threads (7m x 2n
//    warps of 16 tiles x 32 o). Per tap: gen A (fp16, exact) + 3-ring U cp,
//    8 k16 MMAs/warp; AT output fold into 64 fp32 accs/thread.
// ---------------------------------------------------------------------------
#define PSTRIDE 144
#define PWS 58                                // w slots -1..56
#define PROWB (PWS * PSTRIDE)                 // 8352 bytes per patch row
#define PBYTES (10 * PROWB)                   // 83520
#define ASTRIDE 272
#define AB (112 * ASTRIDE)                    // 30464
#define BBY (64 * ASTRIDE)                    // 17408
#define SM_A PBYTES
#define SM_B (PBYTES + 2 * AB)
#define SMEM_DYN (PBYTES + 2 * AB + 3 * BBY)  // 196672

__global__ __launch_bounds__(448)
void wino_fused_kernel(const float* __restrict__ sxp,
                       const float* __restrict__ bias,
                       float* __restrict__ out)
{
    extern __shared__ char sm[];
    uint32_t sb = (uint32_t)__cvta_generic_to_shared(sm);
    int t = threadIdx.x;
    int wid = t >> 5, l = t & 31;
    int wm = wid % 7, wn = wid / 7;
    int o0  = blockIdx.x * 64;                // o fastest -> qx/patch shared in L2
    int ti0 = blockIdx.y * 4;
    int bi  = blockIdx.z;

    // Zero halo columns (w = -1 and w = 56) of the patch
    for (int i = t; i < 640; i += 448) {
        int line = i >> 5;                    // 0..19
        int row = line >> 1, side = line & 1;
        sts32(sb + row * PROWB + (side ? 57 : 0) * PSTRIDE + (i & 31) * 4, 0u);
    }

    // Stage int8 patch: 10 rows x 56 w x 128 c (zfill OOB rows)
    {
        const int8_t* src0 = g_qx + (size_t)bi * HW_ * C_;
#pragma unroll
        for (int i = 0; i < 10; i++) {
            int idx = t + 448 * i;            // 0..4479
            int line = idx >> 3, ch = idx & 7;
            int row = line / 56, w = line - row * 56;
            int ih = 2 * ti0 - 1 + row;
            bool v = (ih >= 0 && ih < H_);
            const void* src = v ? (const void*)(src0 + ((size_t)ih * W_ + w) * C_ + ch * 16)
                               : (const void*)src0;
            cp16z(sb + row * PROWB + (w + 1) * PSTRIDE + ch * 16, src, v ? 16u : 0u);
        }
    }
    cp_commit();                              // G_patch

    // Stage B (U) taps 0,1 into 3-ring
    auto load_B = [&](int tap, int stg) {
        const __half* Us = g_U + ((size_t)tap * O_ + o0) * C_;
        uint32_t base = sb + SM_B + stg * BBY;
#pragma unroll
        for (int i = 0; i < 3; i++) {
            int idx = t + 448 * i;
            if (idx < 1024) {
                int row = idx >> 4, ch = idx & 15;
                cp16(base + row * ASTRIDE + ch * 16, Us + row * C_ + ch * 8);
            }
        }
    };
    load_B(0, 0); cp_commit();
    load_B(1, 1); cp_commit();

    cp_wait<2>();                             // patch resident
    __syncthreads();

    // Per-unit precompute: 8 units/thread, unit = (tile, c-quad)
    uint32_t pbase[8], abase[8];
#pragma unroll
    for (int k = 0; k < 8; k++) {
        int u = t + 448 * k;
        int tile = u >> 5, cq = u & 31;
        int ti_l = tile / 28, tj = tile - ti_l * 28;
        pbase[k] = sb + (2 * ti_l) * PROWB + (2 * tj) * PSTRIDE + cq * 4;
        abase[k] = (uint32_t)(tile * ASTRIDE + cq * 8);
    }

    // A-tile generator for one tap (exact: s16 adds, +1536 fp16 bias trick)
    const __half2 h1536 = __half2half2(__ushort_as_half(0x6600));
    auto gen_tap = [&](int tap, uint32_t abuf) {
        int R = tap >> 2, J = tap & 3;
        int ra = (R == 0) ? 0 : (R == 2) ? 2 : 1;
        int rb = (R == 0) ? 2 : (R == 1) ? 2 : (R == 2) ? 1 : 3;
        bool radd = (R == 1);
        int ca = (J == 0) ? 0 : (J == 2) ? 2 : 1;
        int cb = (J == 0) ? 2 : (J == 1) ? 2 : (J == 2) ? 1 : 3;
        bool cadd = (J == 1);
        uint32_t offAA = (uint32_t)(ra * PROWB + ca * PSTRIDE);
        uint32_t offBA = (uint32_t)(rb * PROWB + ca * PSTRIDE);
        uint32_t offAB = (uint32_t)(ra * PROWB + cb * PSTRIDE);
        uint32_t offBB = (uint32_t)(rb * PROWB + cb * PSTRIDE);
#pragma unroll
        for (int k = 0; k < 8; k++) {
            uint32_t waa = lds32(pbase[k] + offAA);
            uint32_t wba = lds32(pbase[k] + offBA);
            uint32_t wab = lds32(pbase[k] + offAB);
            uint32_t wbb = lds32(pbase[k] + offBB);
            uint32_t aal = prmt0(waa, 0x9180u), aah = prmt0(waa, 0xB3A2u);
            uint32_t bal = prmt0(wba, 0x9180u), bah = prmt0(wba, 0xB3A2u);
            uint32_t abl = prmt0(wab, 0x9180u), abh = prmt0(wab, 0xB3A2u);
            uint32_t bbl = prmt0(wbb, 0x9180u), bbh = prmt0(wbb, 0xB3A2u);
            uint32_t eal = radd ? __vadd2(aal, bal) : __vsub2(aal, bal);
            uint32_t eah = radd ? __vadd2(aah, bah) : __vsub2(aah, bah);
            uint32_t ebl = radd ? __vadd2(abl, bbl) : __vsub2(abl, bbl);
            uint32_t ebh = radd ? __vadd2(abh, bbh) : __vsub2(abh, bbh);
            uint32_t vl = cadd ? __vadd2(eal, ebl) : __vsub2(eal, ebl);
            uint32_t vh = cadd ? __vadd2(eah, ebh) : __vsub2(eah, ebh);
            uint32_t hl = __vadd2(vl, 0x66006600u);
            uint32_t hh = __vadd2(vh, 0x66006600u);
            __half2 rl = __hsub2(*(__half2*)&hl, h1536);
            __half2 rh = __hsub2(*(__half2*)&hh, h1536);
            sts64v(abuf + abase[k], *(uint32_t*)&rl, *(uint32_t*)&rh);
        }
    };

    // Prologue: gen A0, wait B0
    gen_tap(0, sb + SM_A);
    cp_wait<1>();
    __syncthreads();

    float oacc[4][4][4];                      // [ni][q][e]
#pragma unroll
    for (int ni = 0; ni < 4; ni++)
#pragma unroll
        for (int q = 0; q < 4; q++)
#pragma unroll
            for (int e = 0; e < 4; e++) oacc[ni][q][e] = 0.f;

    const float AT0[4] = {1.f, 1.f, 1.f, 0.f};
    const float AT1[4] = {0.f, 1.f, -1.f, -1.f};

    uint32_t aIdx = (uint32_t)((wm * 16 + (l & 15)) * ASTRIDE + (l >> 4) * 16);
    uint32_t bIdx = (uint32_t)((wn * 32 + (l & 7) + (l >> 4) * 8) * ASTRIDE
                               + ((l >> 3) & 1) * 16);

#pragma unroll
    for (int tap = 0; tap < 16; tap++) {
        if (tap + 2 < 16) load_B(tap + 2, (tap + 2) % 3);
        cp_commit();
        if (tap + 1 < 16) gen_tap(tap + 1, sb + SM_A + ((tap + 1) & 1) * AB);

        uint32_t Abuf = sb + SM_A + (tap & 1) * AB;
        uint32_t Bbuf = sb + SM_B + (tap % 3) * BBY;
        float mfr[4][4] = {};
#pragma unroll
        for (int ks = 0; ks < 8; ks++) {
            uint32_t a[4], b0[4], b1[4];
            ldsm4(a,  Abuf + aIdx + ks * 32);
            ldsm4(b0, Bbuf + bIdx + ks * 32);
            ldsm4(b1, Bbuf + bIdx + 16 * ASTRIDE + ks * 32);
            mma_f16(mfr[0], a, b0[0], b0[1]);
            mma_f16(mfr[1], a, b0[2], b0[3]);
            mma_f16(mfr[2], a, b1[0], b1[1]);
            mma_f16(mfr[3], a, b1[2], b1[3]);
        }
        int i_ = tap >> 2, j_ = tap & 3;
        float c00 = AT0[i_] * AT0[j_];
        float c01 = AT0[i_] * AT1[j_];
        float c10 = AT1[i_] * AT0[j_];
        float c11 = AT1[i_] * AT1[j_];
#pragma unroll
        for (int ni = 0; ni < 4; ni++)
#pragma unroll
            for (int q = 0; q < 4; q++) {
                float v = mfr[ni][q];
                oacc[ni][q][0] += c00 * v;
                oacc[ni][q][1] += c01 * v;
                oacc[ni][q][2] += c10 * v;
                oacc[ni][q][3] += c11 * v;
            }
        cp_wait<1>();                         // B[tap+1] resident
        __syncthreads();                      // A[tap+1] visible; bufs free
    }

    // Epilogue: stage to SMEM (stride 261 f32, conflict-free), coalesced writes
    float* ep = (float*)sm;                   // [112 tiles][261]
    int g = l >> 2, tg = l & 3;
#pragma unroll
    for (int ni = 0; ni < 4; ni++)
#pragma unroll
        for (int q = 0; q < 4; q++) {
            int tl = wm * 16 + g + (q >> 1) * 8;
            int ol = wn * 32 + ni * 8 + tg * 2 + (q & 1);
#pragma unroll
            for (int e = 0; e < 4; e++)
                ep[tl * 261 + ol * 4 + e] = oacc[ni][q][e];
        }
    __syncthreads();

    float sx = *sxp;
    int wl = t % 56, ol0 = t / 56;            // 0..55, 0..7
    int tj = wl >> 1, y = wl & 1;
#pragma unroll
    for (int oi = 0; oi < 8; oi++) {
        int ol = ol0 + 8 * oi;
        int o = o0 + ol;
        float sc = sx * g_sw[o];
        float bo = bias[o];
        size_t obase = ((size_t)bi * O_ + o) * HW_ + 2 * tj + y;
#pragma unroll
        for (int ti_l = 0; ti_l < 4; ti_l++)
#pragma unroll
            for (int xx = 0; xx < 2; xx++) {
                float val = ep[(ti_l * 28 + tj) * 261 + ol * 4 + xx * 2 + y];
                out[obase + (size_t)(2 * (ti0 + ti_l) + xx) * W_] = val * sc + bo;
            }
    }
}

// ---------------------------------------------------------------------------
extern "C" void kernel_launch(void* const* d_in, const int* in_sizes, int n_in,
                              void* d_out, int out_size)
{
    const float* x       = (const float*)d_in[0];   // [32,128,56,56]
    const float* weight  = (const float*)d_in[1];   // [256,128,3,3]
    const float* bias    = (const float*)d_in[2];   // [256]
    const float* scale_x = (const float*)d_in[3];   // scalar
    // d_in[4] = lut (unused; fp16 Winograd arithmetic is exact for int8 data)
    float* out = (float*)d_out;

    cudaFuncSetAttribute(wino_fused_kernel,
                         cudaFuncAttributeMaxDynamicSharedMemorySize, SMEM_DYN);

    quant_x_kernel<<<NPOS / 64, 256>>>(x, scale_x);
    wino_w_kernel<<<O_, 128>>>(weight);
    wino_fused_kernel<<<dim3(4, 7, B_), 448, SMEM_DYN>>>(scale_x, bias, out);
}

// round 9
// speedup vs baseline: 1.0499x; 1.0499x over previous
#include <cuda_runtime.h>
#include <cuda_fp16.h>
#include <stdint.h>

#define B_   32
#define C_   128
#define H_   56
#define W_   56
#define O_   256
#define HW_  3136
#define TROW 28          // tiles per row
#define TPI  784         // tiles per image
#define NT   25088       // total 4x4 tiles (B_*TPI)

// Scratch (__device__ globals, allocation-free rule)
__device__ __align__(16) __half g_V[(size_t)16 * NT * 128];   // [tap][tile][c]  ~103MB
__device__ __align__(16) __half g_U[(size_t)16 * O_ * 128];   // [tap][o][c]     1MB
__device__ float g_sw[O_];

// ---------------------------------------------------------------------------
// PTX helpers (base ISA, valid on plain sm_103 target)
// ---------------------------------------------------------------------------
__device__ __forceinline__ void cp16(uint32_t dst, const void* src) {
    asm volatile("cp.async.cg.shared.global [%0], [%1], 16;\n"
                 :: "r"(dst), "l"(__cvta_generic_to_global(src)));
}
__device__ __forceinline__ void cp_commit() { asm volatile("cp.async.commit_group;\n" ::); }
template<int N> __device__ __forceinline__ void cp_wait() {
    asm volatile("cp.async.wait_group %0;\n" :: "n"(N));
}
__device__ __forceinline__ void ldsm4(uint32_t* r, uint32_t addr) {
    asm volatile("ldmatrix.sync.aligned.m8n8.x4.shared.b16 {%0,%1,%2,%3}, [%4];\n"
                 : "=r"(r[0]), "=r"(r[1]), "=r"(r[2]), "=r"(r[3]) : "r"(addr));
}
__device__ __forceinline__ void mma_f16(float* c, const uint32_t* a, uint32_t b0, uint32_t b1) {
    asm volatile("mma.sync.aligned.m16n8k16.row.col.f32.f16.f16.f32 "
                 "{%0,%1,%2,%3}, {%4,%5,%6,%7}, {%8,%9}, {%0,%1,%2,%3};\n"
                 : "+f"(c[0]), "+f"(c[1]), "+f"(c[2]), "+f"(c[3])
                 : "r"(a[0]), "r"(a[1]), "r"(a[2]), "r"(a[3]), "r"(b0), "r"(b1));
}
__device__ __forceinline__ uint32_t lds32(uint32_t addr) {
    uint32_t v;
    asm volatile("ld.shared.b32 %0, [%1];" : "=r"(v) : "r"(addr));
    return v;
}
__device__ __forceinline__ void sts32(uint32_t addr, uint32_t v) {
    asm volatile("st.shared.b32 [%0], %1;" :: "r"(addr), "r"(v));
}
__device__ __forceinline__ uint32_t prmt0(uint32_t a, uint32_t c) {
    uint32_t d;
    asm("prmt.b32 %0, %1, 0, %2;" : "=r"(d) : "r"(a), "r"(c));
    return d;
}

// ---------------------------------------------------------------------------
// 1) x -> quantize -> Winograd input transform -> g_V[tap][tile][c].
//    SMEM patch: int8 [4 rows][58 wslots][128 c], line stride 132B (halo
//    wslots 0 and 57 zeroed). Transform vectorized over channel quads in
//    exact s16x2 arithmetic; fp16 via +0x6600 bias trick (|V| <= 508 exact).
// ---------------------------------------------------------------------------
#define PST 132                       // bytes per (row, wslot) line
#define PRB (58 * PST)                // 7656 bytes per row
#define XSMEM (4 * PRB)               // 30624

__global__ __launch_bounds__(256) void wino_x_kernel(const float* __restrict__ x,
                                                     const float* __restrict__ sxp)
{
    extern __shared__ int8_t sq[];
    uint32_t sb = (uint32_t)__cvta_generic_to_shared(sq);
    int t = threadIdx.x;
    int bi = blockIdx.x / TROW, ti = blockIdx.x % TROW;
    float s = *sxp;

    // Zero halo columns (wslot 0 and 57)
    {
        int row = t >> 6, side = (t >> 5) & 1, word = t & 31;
        sts32(sb + row * PRB + (side ? 57 : 0) * PST + word * 4, 0u);
    }

    // Quantize + stage: 4 rows x 56 w x 128 c int8 (IEEE div, RNE, clamp)
#pragma unroll 4
    for (int i = 0; i < 28; i++) {
        int idx = t + 256 * i;            // 0..7167
        int w = idx % 56;
        int rest = idx / 56;              // 0..127
        int cq = rest & 31, row = rest >> 5;
        int ih = 2 * ti - 1 + row;
        bool valid = (ih >= 0 && ih < H_);
        const float* xp = x + ((size_t)bi * C_ + cq * 4) * HW_ + ih * W_ + w;
        uint32_t pk = 0;
#pragma unroll
        for (int k = 0; k < 4; k++) {
            float v = valid ? xp[(size_t)k * HW_] : 0.f;
            int qi = (int)rintf(v / s);   // true div + RNE == jnp.round(x/s)
            qi = max(-127, min(127, qi));
            pk |= (uint32_t)(qi & 0xFF) << (8 * k);
        }
        sts32(sb + row * PRB + (w + 1) * PST + cq * 4, pk);
    }
    __syncthreads();

    // Transform: item = (tj, channel-quad); 896 items, 4 iterations
    const __half2 h1536 = __half2half2(__ushort_as_half(0x6600));
#pragma unroll
    for (int i = 0; i < 4; i++) {
        int idx = t + 256 * i;
        if (idx >= 896) break;
        int tj = idx >> 5, cq = idx & 31;
        uint32_t pb = sb + (uint32_t)(2 * tj) * PST + cq * 4;

        // Load 4x4 int8-quad block, expand to s16x2 lo/hi
        uint32_t dlo[4][4], dhi[4][4];
#pragma unroll
        for (int r = 0; r < 4; r++)
#pragma unroll
            for (int wc = 0; wc < 4; wc++) {
                uint32_t wv = lds32(pb + r * PRB + wc * PST);
                dlo[r][wc] = prmt0(wv, 0x9180u);
                dhi[r][wc] = prmt0(wv, 0xB3A2u);
            }
        // Row stage: e[r'][wc]
        uint32_t elo[4][4], ehi[4][4];
#pragma unroll
        for (int wc = 0; wc < 4; wc++) {
            elo[0][wc] = __vsub2(dlo[0][wc], dlo[2][wc]);
            elo[1][wc] = __vadd2(dlo[1][wc], dlo[2][wc]);
            elo[2][wc] = __vsub2(dlo[2][wc], dlo[1][wc]);
            elo[3][wc] = __vsub2(dlo[1][wc], dlo[3][wc]);
            ehi[0][wc] = __vsub2(dhi[0][wc], dhi[2][wc]);
            ehi[1][wc] = __vadd2(dhi[1][wc], dhi[2][wc]);
            ehi[2][wc] = __vsub2(dhi[2][wc], dhi[1][wc]);
            ehi[3][wc] = __vsub2(dhi[1][wc], dhi[3][wc]);
        }
        int tid = bi * TPI + ti * TROW + tj;
        __half* vb = g_V + (size_t)tid * 128 + cq * 4;
        // Col stage + fp16 convert + store, tap = r'*4 + j'
#pragma unroll
        for (int r = 0; r < 4; r++) {
            uint32_t vlo[4], vhi[4];
            vlo[0] = __vsub2(elo[r][0], elo[r][2]);
            vlo[1] = __vadd2(elo[r][1], elo[r][2]);
            vlo[2] = __vsub2(elo[r][2], elo[r][1]);
            vlo[3] = __vsub2(elo[r][1], elo[r][3]);
            vhi[0] = __vsub2(ehi[r][0], ehi[r][2]);
            vhi[1] = __vadd2(ehi[r][1], ehi[r][2]);
            vhi[2] = __vsub2(ehi[r][2], ehi[r][1]);
            vhi[3] = __vsub2(ehi[r][1], ehi[r][3]);
#pragma unroll
            for (int j = 0; j < 4; j++) {
                uint32_t bl = __vadd2(vlo[j], 0x66006600u);
                uint32_t bh = __vadd2(vhi[j], 0x66006600u);
                __half2 rl = __hsub2(*(__half2*)&bl, h1536);
                __half2 rh = __hsub2(*(__half2*)&bh, h1536);
                uint2 pair = make_uint2(*(uint32_t*)&rl, *(uint32_t*)&rh);
                *(uint2*)(vb + (size_t)(r * 4 + j) * NT * 128) = pair;
            }
        }
    }
}

// ---------------------------------------------------------------------------
// 2) weight: per-o dynamic scale = max|w|/127, quantize, Winograd filter
//    transform -> g_U[tap][o][c]  (fp16 exact: quarter-multiples, |.| <= 286)
// ---------------------------------------------------------------------------
__global__ __launch_bounds__(128) void wino_w_kernel(const float* __restrict__ w)
{
    int o = blockIdx.x, t = threadIdx.x;
    const float* wo = w + (size_t)o * 1152;

    float m = 0.f;
    for (int i = t; i < 1152; i += 128) m = fmaxf(m, fabsf(wo[i]));
#pragma unroll
    for (int off = 16; off; off >>= 1) m = fmaxf(m, __shfl_xor_sync(0xFFFFFFFFu, m, off));
    __shared__ float red[4];
    if ((t & 31) == 0) red[t >> 5] = m;
    __syncthreads();
    m = fmaxf(fmaxf(red[0], red[1]), fmaxf(red[2], red[3]));
    float scale = m / 127.0f;
    if (t == 0) g_sw[o] = scale;

    int c = t;   // 128 threads == 128 channels
    float g[3][3];
#pragma unroll
    for (int kh = 0; kh < 3; kh++)
#pragma unroll
        for (int kw = 0; kw < 3; kw++) {
            float q = rintf(wo[c * 9 + kh * 3 + kw] / scale);
            g[kh][kw] = fminf(fmaxf(q, -127.f), 127.f);
        }
    float f[4][3];
#pragma unroll
    for (int j = 0; j < 3; j++) {
        f[0][j] = g[0][j];
        f[1][j] = (g[0][j] + g[1][j] + g[2][j]) * 0.5f;
        f[2][j] = (g[0][j] - g[1][j] + g[2][j]) * 0.5f;
        f[3][j] = g[2][j];
    }
#pragma unroll
    for (int r = 0; r < 4; r++) {
        float u0 = f[r][0];
        float u1 = (f[r][0] + f[r][1] + f[r][2]) * 0.5f;
        float u2 = (f[r][0] - f[r][1] + f[r][2]) * 0.5f;
        float u3 = f[r][2];
        g_U[((size_t)(r * 4 + 0) * O_ + o) * 128 + c] = __float2half_rn(u0);
        g_U[((size_t)(r * 4 + 1) * O_ + o) * 128 + c] = __float2half_rn(u1);
        g_U[((size_t)(r * 4 + 2) * O_ + o) * 128 + c] = __float2half_rn(u2);
        g_U[((size_t)(r * 4 + 3) * O_ + o) * 128 + c] = __float2half_rn(u3);
    }
}

// ---------------------------------------------------------------------------
// 3) Winograd GEMM: 16 taps, K=128 each. CTA = 128 tiles x 64 o, 512 threads
//    (16 warps 4x4, warp = 32 tiles x 16 o). Taps as 3-stage cp.async ring;
//    output transform folded incrementally into 64 fp32 accumulators/thread.
// ---------------------------------------------------------------------------
#define GSTRIDE 272                       // bytes per 256B row (+16 pad)
#define GABYTES (128 * GSTRIDE)           // 34816
#define GBBYTES (64 * GSTRIDE)            // 17408
#define GSTAGE  (GABYTES + GBBYTES)       // 52224
#define GSMEM   (3 * GSTAGE)              // 156672 (>= epilogue 133632)

__global__ __launch_bounds__(512)
void wino_gemm_kernel(const float* __restrict__ sxp,
                      const float* __restrict__ bias,
                      float* __restrict__ out)
{
    extern __shared__ char sm[];
    uint32_t sbase = (uint32_t)__cvta_generic_to_shared(sm);
    int t = threadIdx.x;
    int wid = t >> 5, l = t & 31;
    int wm = wid & 3, wn = wid >> 2;      // warp tile: 32 tiles x 16 o
    int o0 = blockIdx.x * 64;             // o-block fastest -> V shared in L2
    int tid0 = blockIdx.y * 128;

    float oacc[2][2][4][4];               // [mi][ni][q][e]
#pragma unroll
    for (int mi = 0; mi < 2; mi++)
#pragma unroll
        for (int ni = 0; ni < 2; ni++)
#pragma unroll
            for (int q = 0; q < 4; q++)
#pragma unroll
                for (int e = 0; e < 4; e++) oacc[mi][ni][q][e] = 0.f;

    // ldsm base addresses (per stage add stg*GSTAGE)
    uint32_t aOff0 = (uint32_t)((wm * 32 + (l & 15)) * GSTRIDE + (l >> 4) * 16);
    uint32_t aOff1 = aOff0 + 16u * GSTRIDE;
    uint32_t bOff  = (uint32_t)(GABYTES + (wn * 16 + (l & 7) + (l >> 4) * 8) * GSTRIDE
                                + ((l >> 3) & 1) * 16);

    auto load_stage = [&](int tap, int stg) {
        const __half* Vs = g_V + ((size_t)tap * NT + tid0) * 128;
        const __half* Us = g_U + ((size_t)tap * O_ + o0) * 128;
        uint32_t base = sbase + stg * GSTAGE;
#pragma unroll
        for (int i = 0; i < 4; i++) {
            int idx = t + 512 * i;        // 0..2047 -> A: 128 rows x 16 chunks
            int row = idx >> 4, jj = idx & 15;
            cp16(base + row * GSTRIDE + jj * 16, Vs + row * 128 + jj * 8);
        }
#pragma unroll
        for (int i = 0; i < 2; i++) {
            int idx = t + 512 * i;        // 0..1023 -> B: 64 rows x 16 chunks
            int row = idx >> 4, jj = idx & 15;
            cp16(base + GABYTES + row * GSTRIDE + jj * 16, Us + row * 128 + jj * 8);
        }
    };

    const float AT0[4] = {1.f, 1.f, 1.f, 0.f};
    const float AT1[4] = {0.f, 1.f, -1.f, -1.f};

    load_stage(0, 0); cp_commit();
    load_stage(1, 1); cp_commit();

#pragma unroll
    for (int tap = 0; tap < 16; tap++) {
        cp_wait<1>();
        __syncthreads();
        if (tap + 2 < 16) load_stage(tap + 2, (tap + 2) % 3);
        cp_commit();

        uint32_t base = sbase + (tap % 3) * GSTAGE;
        float mfr[2][2][4] = {};
#pragma unroll
        for (int ks = 0; ks < 8; ks++) {
            uint32_t a0[4], a1[4], bf[4];
            ldsm4(a0, base + aOff0 + ks * 32);
            ldsm4(a1, base + aOff1 + ks * 32);
            ldsm4(bf, base + bOff  + ks * 32);
            mma_f16(mfr[0][0], a0, bf[0], bf[1]);
            mma_f16(mfr[0][1], a0, bf[2], bf[3]);
            mma_f16(mfr[1][0], a1, bf[0], bf[1]);
            mma_f16(mfr[1][1], a1, bf[2], bf[3]);
        }
        // Incremental output transform: out_xy += AT[x][i]*AT[y][j] * Mhat_ij
        int i_ = tap >> 2, j_ = tap & 3;
        float c00 = AT0[i_] * AT0[j_];
        float c01 = AT0[i_] * AT1[j_];
        float c10 = AT1[i_] * AT0[j_];
        float c11 = AT1[i_] * AT1[j_];
#pragma unroll
        for (int mi = 0; mi < 2; mi++)
#pragma unroll
            for (int ni = 0; ni < 2; ni++)
#pragma unroll
                for (int q = 0; q < 4; q++) {
                    float v = mfr[mi][ni][q];
                    oacc[mi][ni][q][0] += c00 * v;
                    oacc[mi][ni][q][1] += c01 * v;
                    oacc[mi][ni][q][2] += c10 * v;
                    oacc[mi][ni][q][3] += c11 * v;
                }
    }

    // Epilogue: stage in SMEM for coalesced NCHW writes
    __syncthreads();
    float* ep = (float*)sm;               // [128 tiles][261] floats
    int g = l >> 2, tg = l & 3;
#pragma unroll
    for (int mi = 0; mi < 2; mi++)
#pragma unroll
        for (int ni = 0; ni < 2; ni++)
#pragma unroll
            for (int q = 0; q < 4; q++) {
                int tl = wm * 32 + mi * 16 + g + (q >> 1) * 8;
                int ol = wn * 16 + ni * 8 + tg * 2 + (q & 1);
#pragma unroll
                for (int e = 0; e < 4; e++)
                    ep[tl * 261 + ol * 4 + e] = oacc[mi][ni][q][e];
            }
    __syncthreads();

    float sx = *sxp;
    int tile = t >> 2;                    // 0..127
    int xx   = (t >> 1) & 1;
    int y    = t & 1;
    int tidg = tid0 + tile;
    int b  = tidg / TPI;
    int rr = tidg - b * TPI;
    int ti = rr / TROW, tj = rr - ti * TROW;
    size_t obase = (size_t)b * O_ * HW_ + (2 * ti + xx) * W_ + 2 * tj + y;
#pragma unroll 8
    for (int ol = 0; ol < 64; ol++) {
        int o = o0 + ol;
        float val = ep[tile * 261 + ol * 4 + xx * 2 + y];
        out[obase + (size_t)o * HW_] = val * (sx * g_sw[o]) + bias[o];
    }
}

// ---------------------------------------------------------------------------
extern "C" void kernel_launch(void* const* d_in, const int* in_sizes, int n_in,
                              void* d_out, int out_size)
{
    const float* x       = (const float*)d_in[0];   // [32,128,56,56]
    const float* weight  = (const float*)d_in[1];   // [256,128,3,3]
    const float* bias    = (const float*)d_in[2];   // [256]
    const float* scale_x = (const float*)d_in[3];   // scalar
    // d_in[4] = lut (unused; fp16 Winograd arithmetic is exact for int8 data)
    float* out = (float*)d_out;

    cudaFuncSetAttribute(wino_x_kernel,
                         cudaFuncAttributeMaxDynamicSharedMemorySize, XSMEM);
    cudaFuncSetAttribute(wino_gemm_kernel,
                         cudaFuncAttributeMaxDynamicSharedMemorySize, GSMEM);

    wino_x_kernel<<<B_ * TROW, 256, XSMEM>>>(x, scale_x);
    wino_w_kernel<<<O_, 128>>>(weight);
    wino_gemm_kernel<<<dim3(4, NT / 128), 512, GSMEM>>>(scale_x, bias, out);
}

// round 10
// speedup vs baseline: 1.1274x; 1.0739x over previous
#include <cuda_runtime.h>
#include <cuda_fp16.h>
#include <stdint.h>

#define B_   32
#define C_   128
#define H_   56
#define W_   56
#define O_   256
#define HW_  3136
#define TROW 28          // tiles per row
#define TPI  784         // tiles per image
#define NT   25088       // total 4x4 tiles (B_*TPI)

// Scratch (__device__ globals, allocation-free rule)
__device__ __align__(16) __half g_V[(size_t)16 * NT * 128];   // [tap][tile][c]  ~103MB
__device__ __align__(16) __half g_U[(size_t)16 * O_ * 128];   // [tap][o][c]     1MB
__device__ float g_sw[O_];

// ---------------------------------------------------------------------------
// PTX helpers (base ISA, valid on plain sm_103 target)
// ---------------------------------------------------------------------------
__device__ __forceinline__ void cp16(uint32_t dst, const void* src) {
    asm volatile("cp.async.cg.shared.global [%0], [%1], 16;\n"
                 :: "r"(dst), "l"(__cvta_generic_to_global(src)));
}
__device__ __forceinline__ void cp_commit() { asm volatile("cp.async.commit_group;\n" ::); }
template<int N> __device__ __forceinline__ void cp_wait() {
    asm volatile("cp.async.wait_group %0;\n" :: "n"(N));
}
__device__ __forceinline__ void ldsm4(uint32_t* r, uint32_t addr) {
    asm volatile("ldmatrix.sync.aligned.m8n8.x4.shared.b16 {%0,%1,%2,%3}, [%4];\n"
                 : "=r"(r[0]), "=r"(r[1]), "=r"(r[2]), "=r"(r[3]) : "r"(addr));
}
__device__ __forceinline__ void mma_f16(float* c, const uint32_t* a, uint32_t b0, uint32_t b1) {
    asm volatile("mma.sync.aligned.m16n8k16.row.col.f32.f16.f16.f32 "
                 "{%0,%1,%2,%3}, {%4,%5,%6,%7}, {%8,%9}, {%0,%1,%2,%3};\n"
                 : "+f"(c[0]), "+f"(c[1]), "+f"(c[2]), "+f"(c[3])
                 : "r"(a[0]), "r"(a[1]), "r"(a[2]), "r"(a[3]), "r"(b0), "r"(b1));
}

// ---------------------------------------------------------------------------
// 1) x -> quantize -> Winograd input transform -> g_V[tap][tile][c].
//    (R7 version: int8 smem cache, scalar transform — measured 56us.)
// ---------------------------------------------------------------------------
#define XSTRIDE 60       // bytes per (row,c) line
#define XSMEM (4 * 128 * XSTRIDE)   // 30720 B

__global__ __launch_bounds__(256) void wino_x_kernel(const float* __restrict__ x,
                                                     const float* __restrict__ sxp)
{
    extern __shared__ int8_t sq[];
    int t = threadIdx.x;
    int bi = blockIdx.x / TROW, ti = blockIdx.x % TROW;
    float s = *sxp;

    // Load + quantize: 4 rows (2ti-1..2ti+2) x 128 ch x 56 w -> int8 smem
#pragma unroll 4
    for (int i = 0; i < 28; i++) {
        int idx = t + 256 * i;             // 0..7167 = 4*128*14-1
        int w4 = idx % 14;
        int cr = idx / 14;
        int c = cr & 127, j = cr >> 7;
        int row = 2 * ti - 1 + j;
        float4 v = make_float4(0.f, 0.f, 0.f, 0.f);
        if (row >= 0 && row < H_)
            v = *(const float4*)(x + ((size_t)bi * C_ + c) * HW_ + row * W_ + w4 * 4);
        int q0 = (int)fminf(fmaxf(rintf(v.x / s), -127.f), 127.f);
        int q1 = (int)fminf(fmaxf(rintf(v.y / s), -127.f), 127.f);
        int q2 = (int)fminf(fmaxf(rintf(v.z / s), -127.f), 127.f);
        int q3 = (int)fminf(fmaxf(rintf(v.w / s), -127.f), 127.f);
        uint32_t pk = (uint32_t)(q0 & 0xFF) | ((uint32_t)(q1 & 0xFF) << 8)
                    | ((uint32_t)(q2 & 0xFF) << 16) | ((uint32_t)(q3 & 0xFF) << 24);
        *(uint32_t*)(sq + (j * 128 + c) * XSTRIDE + w4 * 4) = pk;
    }
    __syncthreads();

    // Transform: item = (tj, c)
#pragma unroll 2
    for (int i = 0; i < 14; i++) {
        int idx = t + 256 * i;             // 0..3583
        int c = idx & 127, tj = idx >> 7;
        float d[4][4];
#pragma unroll
        for (int r = 0; r < 4; r++)
#pragma unroll
            for (int wc = 0; wc < 4; wc++) {
                int w = 2 * tj - 1 + wc;
                d[r][wc] = (w >= 0 && w < W_)
                    ? (float)sq[(r * 128 + c) * XSTRIDE + w] : 0.f;
            }
        float e[4][4];
#pragma unroll
        for (int j = 0; j < 4; j++) {
            e[0][j] = d[0][j] - d[2][j];
            e[1][j] = d[1][j] + d[2][j];
            e[2][j] = d[2][j] - d[1][j];
            e[3][j] = d[1][j] - d[3][j];
        }
        float vv[4][4];
#pragma unroll
        for (int r = 0; r < 4; r++) {
            vv[r][0] = e[r][0] - e[r][2];
            vv[r][1] = e[r][1] + e[r][2];
            vv[r][2] = e[r][2] - e[r][1];
            vv[r][3] = e[r][1] - e[r][3];
        }
        int tid = bi * TPI + ti * TROW + tj;
#pragma unroll
        for (int r = 0; r < 4; r++)
#pragma unroll
            for (int j = 0; j < 4; j++)
                g_V[((size_t)(r * 4 + j) * NT + tid) * 128 + c] = __float2half_rn(vv[r][j]);
    }
}

// ---------------------------------------------------------------------------
// 2) weight: per-o dynamic scale = max|w|/127, quantize, Winograd filter
//    transform -> g_U[tap][o][c]  (fp16 exact: quarter-multiples, |.| <= 286)
// ---------------------------------------------------------------------------
__global__ __launch_bounds__(128) void wino_w_kernel(const float* __restrict__ w)
{
    int o = blockIdx.x, t = threadIdx.x;
    const float* wo = w + (size_t)o * 1152;

    float m = 0.f;
    for (int i = t; i < 1152; i += 128) m = fmaxf(m, fabsf(wo[i]));
#pragma unroll
    for (int off = 16; off; off >>= 1) m = fmaxf(m, __shfl_xor_sync(0xFFFFFFFFu, m, off));
    __shared__ float red[4];
    if ((t & 31) == 0) red[t >> 5] = m;
    __syncthreads();
    m = fmaxf(fmaxf(red[0], red[1]), fmaxf(red[2], red[3]));
    float scale = m / 127.0f;
    if (t == 0) g_sw[o] = scale;

    int c = t;   // 128 threads == 128 channels
    float g[3][3];
#pragma unroll
    for (int kh = 0; kh < 3; kh++)
#pragma unroll
        for (int kw = 0; kw < 3; kw++) {
            float q = rintf(wo[c * 9 + kh * 3 + kw] / scale);
            g[kh][kw] = fminf(fmaxf(q, -127.f), 127.f);
        }
    float f[4][3];
#pragma unroll
    for (int j = 0; j < 3; j++) {
        f[0][j] = g[0][j];
        f[1][j] = (g[0][j] + g[1][j] + g[2][j]) * 0.5f;
        f[2][j] = (g[0][j] - g[1][j] + g[2][j]) * 0.5f;
        f[3][j] = g[2][j];
    }
#pragma unroll
    for (int r = 0; r < 4; r++) {
        float u0 = f[r][0];
        float u1 = (f[r][0] + f[r][1] + f[r][2]) * 0.5f;
        float u2 = (f[r][0] - f[r][1] + f[r][2]) * 0.5f;
        float u3 = f[r][2];
        g_U[((size_t)(r * 4 + 0) * O_ + o) * 128 + c] = __float2half_rn(u0);
        g_U[((size_t)(r * 4 + 1) * O_ + o) * 128 + c] = __float2half_rn(u1);
        g_U[((size_t)(r * 4 + 2) * O_ + o) * 128 + c] = __float2half_rn(u2);
        g_U[((size_t)(r * 4 + 3) * O_ + o) * 128 + c] = __float2half_rn(u3);
    }
}

// ---------------------------------------------------------------------------
// 3) Winograd GEMM: 16 taps, K=128. CTA = 128 tiles x 64 o, 256 threads
//    (8 warps 4m x 2n, warp = 32 tiles x 32 o). 3-stage cp.async ring;
//    AT output fold incrementally into 128 fp32 accumulators/thread.
// ---------------------------------------------------------------------------
#define GSTRIDE 272                       // bytes per 256B row (+16 pad)
#define GABYTES (128 * GSTRIDE)           // 34816
#define GBBYTES (64 * GSTRIDE)            // 17408
#define GSTAGE  (GABYTES + GBBYTES)       // 52224
#define GSMEM   (3 * GSTAGE)              // 156672 (>= epilogue 133632)

__global__ __launch_bounds__(256, 1)
void wino_gemm_kernel(const float* __restrict__ sxp,
                      const float* __restrict__ bias,
                      float* __restrict__ out)
{
    extern __shared__ char sm[];
    uint32_t sbase = (uint32_t)__cvta_generic_to_shared(sm);
    int t = threadIdx.x;
    int wid = t >> 5, l = t & 31;
    int wm = wid & 3, wn = wid >> 2;      // warp tile: 32 tiles x 32 o
    int o0 = blockIdx.x * 64;             // o-block fastest -> V shared in L2
    int tid0 = blockIdx.y * 128;

    float oacc[2][4][4][4];               // [mi][ni][q][e]
#pragma unroll
    for (int mi = 0; mi < 2; mi++)
#pragma unroll
        for (int ni = 0; ni < 4; ni++)
#pragma unroll
            for (int q = 0; q < 4; q++)
#pragma unroll
                for (int e = 0; e < 4; e++) oacc[mi][ni][q][e] = 0.f;

    // ldsm base addresses (per stage add stg*GSTAGE)
    uint32_t aOff0 = (uint32_t)((wm * 32 + (l & 15)) * GSTRIDE + (l >> 4) * 16);
    uint32_t aOff1 = aOff0 + 16u * GSTRIDE;
    uint32_t bOff0 = (uint32_t)(GABYTES + (wn * 32 + (l & 7) + (l >> 4) * 8) * GSTRIDE
                                + ((l >> 3) & 1) * 16);
    uint32_t bOff1 = bOff0 + 16u * GSTRIDE;

    auto load_stage = [&](int tap, int stg) {
        const __half* Vs = g_V + ((size_t)tap * NT + tid0) * 128;
        const __half* Us = g_U + ((size_t)tap * O_ + o0) * 128;
        uint32_t base = sbase + stg * GSTAGE;
#pragma unroll
        for (int i = 0; i < 8; i++) {
            int idx = t + 256 * i;        // 0..2047 -> A: 128 rows x 16 chunks
            int row = idx >> 4, jj = idx & 15;
            cp16(base + row * GSTRIDE + jj * 16, Vs + row * 128 + jj * 8);
        }
#pragma unroll
        for (int i = 0; i < 4; i++) {
            int idx = t + 256 * i;        // 0..1023 -> B: 64 rows x 16 chunks
            int row = idx >> 4, jj = idx & 15;
            cp16(base + GABYTES + row * GSTRIDE + jj * 16, Us + row * 128 + jj * 8);
        }
    };

    const float AT0[4] = {1.f, 1.f, 1.f, 0.f};
    const float AT1[4] = {0.f, 1.f, -1.f, -1.f};

    load_stage(0, 0); cp_commit();
    load_stage(1, 1); cp_commit();

#pragma unroll
    for (int tap = 0; tap < 16; tap++) {
        cp_wait<1>();
        __syncthreads();
        if (tap + 2 < 16) load_stage(tap + 2, (tap + 2) % 3);
        cp_commit();

        uint32_t base = sbase + (tap % 3) * GSTAGE;
        float mfr[2][4][4] = {};
#pragma unroll
        for (int ks = 0; ks < 8; ks++) {
            uint32_t a0[4], a1[4], b0[4], b1[4];
            ldsm4(a0, base + aOff0 + ks * 32);
            ldsm4(a1, base + aOff1 + ks * 32);
            ldsm4(b0, base + bOff0 + ks * 32);
            ldsm4(b1, base + bOff1 + ks * 32);
            mma_f16(mfr[0][0], a0, b0[0], b0[1]);
            mma_f16(mfr[0][1], a0, b0[2], b0[3]);
            mma_f16(mfr[0][2], a0, b1[0], b1[1]);
            mma_f16(mfr[0][3], a0, b1[2], b1[3]);
            mma_f16(mfr[1][0], a1, b0[0], b0[1]);
            mma_f16(mfr[1][1], a1, b0[2], b0[3]);
            mma_f16(mfr[1][2], a1, b1[0], b1[1]);
            mma_f16(mfr[1][3], a1, b1[2], b1[3]);
        }
        // Incremental output transform: out_xy += AT[x][i]*AT[y][j] * Mhat_ij
        int i_ = tap >> 2, j_ = tap & 3;
        float c00 = AT0[i_] * AT0[j_];
        float c01 = AT0[i_] * AT1[j_];
        float c10 = AT1[i_] * AT0[j_];
        float c11 = AT1[i_] * AT1[j_];
#pragma unroll
        for (int mi = 0; mi < 2; mi++)
#pragma unroll
            for (int ni = 0; ni < 4; ni++)
#pragma unroll
                for (int q = 0; q < 4; q++) {
                    float v = mfr[mi][ni][q];
                    oacc[mi][ni][q][0] += c00 * v;
                    oacc[mi][ni][q][1] += c01 * v;
                    oacc[mi][ni][q][2] += c10 * v;
                    oacc[mi][ni][q][3] += c11 * v;
                }
    }

    // Epilogue: stage in SMEM for coalesced NCHW writes
    __syncthreads();
    float* ep = (float*)sm;               // [128 tiles][261] floats
    int g = l >> 2, tg = l & 3;
#pragma unroll
    for (int mi = 0; mi < 2; mi++)
#pragma unroll
        for (int ni = 0; ni < 4; ni++)
#pragma unroll
            for (int q = 0; q < 4; q++) {
                int tl = wm * 32 + mi * 16 + g + (q >> 1) * 8;
                int ol = wn * 32 + ni * 8 + tg * 2 + (q & 1);
#pragma unroll
                for (int e = 0; e < 4; e++)
                    ep[tl * 261 + ol * 4 + e] = oacc[mi][ni][q][e];
            }
    __syncthreads();

    float sx = *sxp;
    int tile = t >> 1;                    // 0..127
    int y    = t & 1;
    int tidg = tid0 + tile;
    int b  = tidg / TPI;
    int rr = tidg - b * TPI;
    int ti = rr / TROW, tj = rr - ti * TROW;
    size_t obase = (size_t)b * O_ * HW_ + 2 * ti * W_ + 2 * tj + y;
#pragma unroll 8
    for (int ol = 0; ol < 64; ol++) {
        int o = o0 + ol;
        float sc = sx * g_sw[o];
        float bo = bias[o];
        size_t ob = obase + (size_t)o * HW_;
        out[ob]      = ep[tile * 261 + ol * 4 + y]     * sc + bo;   // xx=0
        out[ob + W_] = ep[tile * 261 + ol * 4 + 2 + y] * sc + bo;   // xx=1
    }
}

// ---------------------------------------------------------------------------
extern "C" void kernel_launch(void* const* d_in, const int* in_sizes, int n_in,
                              void* d_out, int out_size)
{
    const float* x       = (const float*)d_in[0];   // [32,128,56,56]
    const float* weight  = (const float*)d_in[1];   // [256,128,3,3]
    const float* bias    = (const float*)d_in[2];   // [256]
    const float* scale_x = (const float*)d_in[3];   // scalar
    // d_in[4] = lut (unused; fp16 Winograd arithmetic is exact for int8 data)
    float* out = (float*)d_out;

    cudaFuncSetAttribute(wino_x_kernel,
                         cudaFuncAttributeMaxDynamicSharedMemorySize, XSMEM);
    cudaFuncSetAttribute(wino_gemm_kernel,
                         cudaFuncAttributeMaxDynamicSharedMemorySize, GSMEM);

    wino_x_kernel<<<B_ * TROW, 256, XSMEM>>>(x, scale_x);
    wino_w_kernel<<<O_, 128>>>(weight);
    wino_gemm_kernel<<<dim3(4, NT / 128), 256, GSMEM>>>(scale_x, bias, out);
}